// round 4
// baseline (speedup 1.0000x reference)
#include <cuda_runtime.h>
#include <cstdint>

#define Bb   32
#define Ss   512
#define INP  512
#define Hh   1024
#define Gg   3072
#define Ll   4
#define RS   (Bb*Ss)
#define PADK 36

// persistent recurrence kernel config
#define NB   128          // blocks (<=148 SMs, 1 CTA/SM resident -> barrier safe)
#define NT   256
#define RPB  24           // gate rows per block (3072/128), divisible by 3
#define UPB  8            // hidden units per block
#define KC2  128          // k-chunk of h staged in smem
#define NC2  (Hh/KC2)     // 8 chunks
#define WST  1028         // W smem row stride (floats)
#define HST2 132          // h smem row stride (words)
#define RST  25           // partial row stride

// ---------------- device scratch ----------------
__device__ float g_gates[(size_t)RS * Gg];      // 192 MiB
__device__ float g_y0[(size_t)RS * Hh];
__device__ float g_y1[(size_t)RS * Hh];
__device__ float g_hbuf[2 * Bb * Hh];           // ping-pong recurrent h (fp32)
__device__ float g_wih0p[Gg * INP];
__device__ float g_wihp[(Ll - 1) * Gg * Hh];
__device__ float g_whhp[(size_t)Ll * Gg * Hh];
__device__ float g_bp[Ll * Gg];
__device__ unsigned g_bar[2];                   // [0]=count, [1]=gen

// ---------------- helpers ----------------
__device__ __forceinline__ unsigned f2tf(float f) {
    unsigned u;
    asm("cvt.rna.tf32.f32 %0, %1;" : "=r"(u) : "f"(f));
    return u;
}
// split fp32 -> (hi, lo) tf32 pair; hi+lo represents x to ~2^-22
__device__ __forceinline__ void split_tf(float x, unsigned& hi, unsigned& lo) {
    hi = f2tf(x);
    lo = f2tf(x - __uint_as_float(hi));
}
__device__ __forceinline__ void mma_tf32(float c[4],
                                         unsigned a0, unsigned a1, unsigned a2, unsigned a3,
                                         unsigned b0, unsigned b1) {
    asm volatile(
        "mma.sync.aligned.m16n8k8.row.col.f32.tf32.tf32.f32 "
        "{%0,%1,%2,%3}, {%4,%5,%6,%7}, {%8,%9}, {%0,%1,%2,%3};\n"
        : "+f"(c[0]), "+f"(c[1]), "+f"(c[2]), "+f"(c[3])
        : "r"(a0), "r"(a1), "r"(a2), "r"(a3), "r"(b0), "r"(b1));
}
__device__ __forceinline__ float sigf(float x) { return 1.0f / (1.0f + expf(-x)); }

// ---------------- weight reorder: row n' = 3*h + gate ----------------
__global__ void reorder_w4(const float4* __restrict__ src, float4* __restrict__ dst, int K4) {
    int total = Gg * K4;
    for (int i = blockIdx.x * blockDim.x + threadIdx.x; i < total; i += gridDim.x * blockDim.x) {
        int np = i / K4;
        int k  = i - np * K4;
        int h  = np / 3;
        int g  = np - h * 3;
        dst[i] = src[(size_t)(g * Hh + h) * K4 + k];
    }
}
__global__ void reorder_b(const float* __restrict__ src, float* __restrict__ dst) {
    int i = blockIdx.x * blockDim.x + threadIdx.x;
    if (i < Gg) {
        int h = i / 3, g = i - h * 3;
        dst[i] = src[g * Hh + h];
    }
}

// ---------------- input projection GEMM (3xTF32): out = X @ W'^T + b' ----------------
__global__ __launch_bounds__(256) void gemm_input(const float* __restrict__ X,
                                                  const float* __restrict__ W,
                                                  const float* __restrict__ bias,
                                                  float* __restrict__ out,
                                                  int K) {
    extern __shared__ unsigned gsm[];
    unsigned* AsH = gsm;                       // [128][PADK]
    unsigned* AsL = gsm + 128 * PADK;
    unsigned* BsH = gsm + 2 * 128 * PADK;
    unsigned* BsL = gsm + 3 * 128 * PADK;

    const int tid  = threadIdx.x;
    const int warp = tid >> 5, lane = tid & 31;
    const int gq = lane >> 2, tq = lane & 3;
    const int wm = (warp & 1) * 64;
    const int wn = (warp >> 1) * 32;
    const int rowBase = blockIdx.y * 128;
    const int colBase = blockIdx.x * 128;

    float C[4][4][4];
#pragma unroll
    for (int mf = 0; mf < 4; mf++)
#pragma unroll
        for (int nf = 0; nf < 4; nf++)
#pragma unroll
            for (int q = 0; q < 4; q++) C[mf][nf][q] = 0.0f;

    const int lr = tid >> 1;
    const int lc = (tid & 1) * 16;
    const float* Xp = X + (size_t)(rowBase + lr) * K + lc;
    const float* Wp = W + (size_t)(colBase + lr) * K + lc;

    for (int k0 = 0; k0 < K; k0 += 32) {
#pragma unroll
        for (int v = 0; v < 4; v++) {
            float4 xa = *(const float4*)(Xp + k0 + v * 4);
            unsigned h0, l0, h1, l1, h2, l2, h3, l3;
            split_tf(xa.x, h0, l0); split_tf(xa.y, h1, l1);
            split_tf(xa.z, h2, l2); split_tf(xa.w, h3, l3);
            *(uint4*)&AsH[lr * PADK + lc + v * 4] = make_uint4(h0, h1, h2, h3);
            *(uint4*)&AsL[lr * PADK + lc + v * 4] = make_uint4(l0, l1, l2, l3);
            float4 wb = *(const float4*)(Wp + k0 + v * 4);
            split_tf(wb.x, h0, l0); split_tf(wb.y, h1, l1);
            split_tf(wb.z, h2, l2); split_tf(wb.w, h3, l3);
            *(uint4*)&BsH[lr * PADK + lc + v * 4] = make_uint4(h0, h1, h2, h3);
            *(uint4*)&BsL[lr * PADK + lc + v * 4] = make_uint4(l0, l1, l2, l3);
        }
        __syncthreads();

#pragma unroll
        for (int kc = 0; kc < 32; kc += 8) {
            unsigned aH[4][4], aL[4][4], bH[4][2], bL[4][2];
#pragma unroll
            for (int mf = 0; mf < 4; mf++) {
                int m0 = wm + mf * 16 + gq;
                aH[mf][0] = AsH[m0 * PADK + kc + tq];
                aH[mf][1] = AsH[(m0 + 8) * PADK + kc + tq];
                aH[mf][2] = AsH[m0 * PADK + kc + tq + 4];
                aH[mf][3] = AsH[(m0 + 8) * PADK + kc + tq + 4];
                aL[mf][0] = AsL[m0 * PADK + kc + tq];
                aL[mf][1] = AsL[(m0 + 8) * PADK + kc + tq];
                aL[mf][2] = AsL[m0 * PADK + kc + tq + 4];
                aL[mf][3] = AsL[(m0 + 8) * PADK + kc + tq + 4];
            }
#pragma unroll
            for (int nf = 0; nf < 4; nf++) {
                int n0 = wn + nf * 8 + gq;
                bH[nf][0] = BsH[n0 * PADK + kc + tq];
                bH[nf][1] = BsH[n0 * PADK + kc + tq + 4];
                bL[nf][0] = BsL[n0 * PADK + kc + tq];
                bL[nf][1] = BsL[n0 * PADK + kc + tq + 4];
            }
#pragma unroll
            for (int mf = 0; mf < 4; mf++)
#pragma unroll
                for (int nf = 0; nf < 4; nf++) {
                    mma_tf32(C[mf][nf], aH[mf][0], aH[mf][1], aH[mf][2], aH[mf][3],
                             bH[nf][0], bH[nf][1]);
                    mma_tf32(C[mf][nf], aL[mf][0], aL[mf][1], aL[mf][2], aL[mf][3],
                             bH[nf][0], bH[nf][1]);
                    mma_tf32(C[mf][nf], aH[mf][0], aH[mf][1], aH[mf][2], aH[mf][3],
                             bL[nf][0], bL[nf][1]);
                }
        }
        __syncthreads();
    }

#pragma unroll
    for (int mf = 0; mf < 4; mf++) {
#pragma unroll
        for (int nf = 0; nf < 4; nf++) {
            int r0 = rowBase + wm + mf * 16 + gq;
            int c0 = colBase + wn + nf * 8 + 2 * tq;
            float bi0 = bias[c0], bi1 = bias[c0 + 1];
            *(float2*)&out[(size_t)r0 * Gg + c0] =
                make_float2(C[mf][nf][0] + bi0, C[mf][nf][1] + bi1);
            *(float2*)&out[(size_t)(r0 + 8) * Gg + c0] =
                make_float2(C[mf][nf][2] + bi0, C[mf][nf][3] + bi1);
        }
    }
}

// ---------------- persistent per-layer recurrence (3xTF32) ----------------
// W slice resident fp32 in SMEM (split to tf32 hi/lo per use); h staged per
// step in hi/lo tf32 chunks; c in registers; grid barrier per step.
__global__ __launch_bounds__(NT, 1) void lstm_layer(const float* __restrict__ gates,
                                                    const float* __restrict__ W,
                                                    float* __restrict__ y,
                                                    float* __restrict__ hf,
                                                    float* __restrict__ cf) {
    extern __shared__ unsigned sm[];
    float*    Wsm  = (float*)sm;                       // RPB x WST fp32
    unsigned* Hbuf = sm + RPB * WST;                   // [2 buf][hi/lo][32][HST2]
    float*    Rsm  = (float*)(sm + RPB * WST + 4 * 32 * HST2);  // 8 x 32 x RST

    const int tid  = threadIdx.x;
    const int warp = tid >> 5, lane = tid & 31;
    const int gq = lane >> 2, tq = lane & 3;
    const int kw = warp;                 // 0..7 k-split
    const int blk = blockIdx.x;
    const int npBase = blk * RPB;
    const int hBase  = blk * UPB;
    const int eb = tid >> 3;             // epilogue batch 0..31
    const int eu = tid & 7;              // epilogue unit 0..7

    // --- load W slice (fp32) to SMEM once ---
    {
        const float4* Wp = (const float4*)(W + (size_t)npBase * Hh);
        for (int i = tid; i < RPB * Hh / 4; i += NT) {
            int r  = i >> 8;
            int c4 = i & 255;
            *(float4*)&Wsm[r * WST + c4 * 4] = Wp[i];
        }
    }
    __syncthreads();

    float creg = 0.0f;
    unsigned gen = 0;
    const float* gpt = gates + (size_t)eb * Ss * Gg + npBase + 3 * eu;

    for (int t = 0; t < Ss; t++) {
        const float* gp = gpt + (size_t)t * Gg;
        float gi = __ldg(gp);
        float gg = __ldg(gp + 1);
        float go = __ldg(gp + 2);

        if (t > 0) {
            float C[2][3][4];
#pragma unroll
            for (int mf = 0; mf < 2; mf++)
#pragma unroll
                for (int nf = 0; nf < 3; nf++)
#pragma unroll
                    for (int q = 0; q < 4; q++) C[mf][nf][q] = 0.0f;

            const float4* hp = (const float4*)(g_hbuf + ((t - 1) & 1) * Bb * Hh);

            // stage chunk 0 (32 rows x 128 k = 1024 float4)
            {
#pragma unroll
                for (int j = 0; j < 4; j++) {
                    int idx = tid + j * NT;
                    int row = idx >> 5, c4 = idx & 31;
                    float4 f = hp[row * (Hh / 4) + c4];
                    unsigned h0, l0, h1, l1, h2, l2, h3, l3;
                    split_tf(f.x, h0, l0); split_tf(f.y, h1, l1);
                    split_tf(f.z, h2, l2); split_tf(f.w, h3, l3);
                    unsigned* hi = Hbuf;                 // buf0 hi
                    unsigned* lo = Hbuf + 32 * HST2;     // buf0 lo
                    *(uint4*)&hi[row * HST2 + c4 * 4] = make_uint4(h0, h1, h2, h3);
                    *(uint4*)&lo[row * HST2 + c4 * 4] = make_uint4(l0, l1, l2, l3);
                }
            }
            __syncthreads();

            float4 rg[4];
#pragma unroll
            for (int ch = 0; ch < NC2; ch++) {
                if (ch + 1 < NC2) {
#pragma unroll
                    for (int j = 0; j < 4; j++) {
                        int idx = tid + j * NT;
                        int row = idx >> 5, c4 = idx & 31;
                        rg[j] = hp[row * (Hh / 4) + (ch + 1) * 32 + c4];
                    }
                }
                const unsigned* HbH = Hbuf + (ch & 1) * 2 * 32 * HST2;
                const unsigned* HbL = HbH + 32 * HST2;
                const float*    Wb  = Wsm + ch * KC2;
#pragma unroll
                for (int s = 0; s < 2; s++) {
                    int kc = (kw + s * 8) << 3;      // 0..120 within chunk
                    unsigned aH[2][4], aL[2][4];
#pragma unroll
                    for (int mf = 0; mf < 2; mf++) {
                        int r0 = mf * 16 + gq;
                        aH[mf][0] = HbH[r0 * HST2 + kc + tq];
                        aH[mf][1] = HbH[(r0 + 8) * HST2 + kc + tq];
                        aH[mf][2] = HbH[r0 * HST2 + kc + tq + 4];
                        aH[mf][3] = HbH[(r0 + 8) * HST2 + kc + tq + 4];
                        aL[mf][0] = HbL[r0 * HST2 + kc + tq];
                        aL[mf][1] = HbL[(r0 + 8) * HST2 + kc + tq];
                        aL[mf][2] = HbL[r0 * HST2 + kc + tq + 4];
                        aL[mf][3] = HbL[(r0 + 8) * HST2 + kc + tq + 4];
                    }
#pragma unroll
                    for (int nf = 0; nf < 3; nf++) {
                        int n0 = nf * 8 + gq;
                        float w0 = Wb[n0 * WST + kc + tq];
                        float w1 = Wb[n0 * WST + kc + tq + 4];
                        unsigned bh0, bl0, bh1, bl1;
                        split_tf(w0, bh0, bl0);
                        split_tf(w1, bh1, bl1);
#pragma unroll
                        for (int mf = 0; mf < 2; mf++) {
                            mma_tf32(C[mf][nf], aH[mf][0], aH[mf][1], aH[mf][2], aH[mf][3], bh0, bh1);
                            mma_tf32(C[mf][nf], aL[mf][0], aL[mf][1], aL[mf][2], aL[mf][3], bh0, bh1);
                            mma_tf32(C[mf][nf], aH[mf][0], aH[mf][1], aH[mf][2], aH[mf][3], bl0, bl1);
                        }
                    }
                }
                __syncthreads();
                if (ch + 1 < NC2) {
                    unsigned* hi = Hbuf + ((ch + 1) & 1) * 2 * 32 * HST2;
                    unsigned* lo = hi + 32 * HST2;
#pragma unroll
                    for (int j = 0; j < 4; j++) {
                        int idx = tid + j * NT;
                        int row = idx >> 5, c4 = idx & 31;
                        unsigned h0, l0, h1, l1, h2, l2, h3, l3;
                        split_tf(rg[j].x, h0, l0); split_tf(rg[j].y, h1, l1);
                        split_tf(rg[j].z, h2, l2); split_tf(rg[j].w, h3, l3);
                        *(uint4*)&hi[row * HST2 + c4 * 4] = make_uint4(h0, h1, h2, h3);
                        *(uint4*)&lo[row * HST2 + c4 * 4] = make_uint4(l0, l1, l2, l3);
                    }
                    __syncthreads();
                }
            }

            // dump k-split partials
#pragma unroll
            for (int mf = 0; mf < 2; mf++)
#pragma unroll
                for (int nf = 0; nf < 3; nf++) {
                    int rrow = mf * 16 + gq;
                    int rcol = nf * 8 + 2 * tq;
                    float* p  = &Rsm[(kw * 32 + rrow) * RST + rcol];
                    p[0] = C[mf][nf][0]; p[1] = C[mf][nf][1];
                    float* p2 = &Rsm[(kw * 32 + rrow + 8) * RST + rcol];
                    p2[0] = C[mf][nf][2]; p2[1] = C[mf][nf][3];
                }
            __syncthreads();
        }

        // fused CEC activation (thread owns (batch eb, unit eu); c in reg)
        float iv = gi, gv = gg, ov = go;
        if (t > 0) {
#pragma unroll
            for (int k2 = 0; k2 < 8; k2++) {
                const float* rr = &Rsm[(k2 * 32 + eb) * RST + 3 * eu];
                iv += rr[0]; gv += rr[1]; ov += rr[2];
            }
        }
        creg += sigf(iv) * tanhf(gv);
        float h = sigf(ov) * tanhf(creg);
        const int hidx = hBase + eu;
        g_hbuf[(t & 1) * Bb * Hh + eb * Hh + hidx] = h;
        y[((size_t)eb * Ss + t) * Hh + hidx] = h;
        if (t == Ss - 1) {
            if (hf) hf[eb * Hh + hidx] = h;
            if (cf) cf[eb * Hh + hidx] = creg;
        }

        if (t < Ss - 1) {
            gen++;
            __syncthreads();
            if (tid == 0) {
                __threadfence();
                unsigned a = atomicAdd(&g_bar[0], 1);
                if (a == NB * gen - 1) {
                    asm volatile("st.release.gpu.u32 [%0], %1;" ::
                                 "l"(&g_bar[1]), "r"(gen) : "memory");
                } else {
                    unsigned v;
                    do {
                        asm volatile("ld.acquire.gpu.u32 %0, [%1];"
                                     : "=r"(v) : "l"(&g_bar[1]) : "memory");
                    } while (v < gen);
                }
            }
            __syncthreads();
        }
    }
}

// ---------------- host ----------------
extern "C" void kernel_launch(void* const* d_in, const int* in_sizes, int n_in,
                              void* d_out, int out_size) {
    const float* x         = (const float*)d_in[0];
    const float* w_ih0     = (const float*)d_in[1];
    const float* w_hh0     = (const float*)d_in[2];
    const float* b0        = (const float*)d_in[3];
    const float* w_ih_rest = (const float*)d_in[4];
    const float* w_hh_rest = (const float*)d_in[5];
    const float* b_rest    = (const float*)d_in[6];
    float* out = (float*)d_out;

    float *gates, *y0, *y1, *wih0p, *wihp, *whhp, *bp;
    unsigned* bar;
    cudaGetSymbolAddress((void**)&gates, g_gates);
    cudaGetSymbolAddress((void**)&y0, g_y0);
    cudaGetSymbolAddress((void**)&y1, g_y1);
    cudaGetSymbolAddress((void**)&wih0p, g_wih0p);
    cudaGetSymbolAddress((void**)&wihp, g_wihp);
    cudaGetSymbolAddress((void**)&whhp, g_whhp);
    cudaGetSymbolAddress((void**)&bp, g_bp);
    cudaGetSymbolAddress((void**)&bar, g_bar);

    const int SMEMB_L = (RPB * WST + 4 * 32 * HST2 + 8 * 32 * RST) * 4;  // 191872 B
    const int SMEMB_G = 4 * 128 * PADK * 4;                              // 73728 B
    cudaFuncSetAttribute(lstm_layer, cudaFuncAttributeMaxDynamicSharedMemorySize, SMEMB_L);
    cudaFuncSetAttribute(gemm_input, cudaFuncAttributeMaxDynamicSharedMemorySize, SMEMB_G);

    // weight/bias reorder (gate-interleaved rows)
    reorder_w4<<<512, 256>>>((const float4*)w_ih0, (float4*)wih0p, INP / 4);
    reorder_w4<<<512, 256>>>((const float4*)w_hh0, (float4*)whhp, Hh / 4);
    reorder_b<<<12, 256>>>(b0, bp);
    for (int l = 1; l < Ll; l++) {
        reorder_w4<<<512, 256>>>((const float4*)(w_ih_rest + (size_t)(l - 1) * Gg * Hh),
                                 (float4*)(wihp + (size_t)(l - 1) * Gg * Hh), Hh / 4);
        reorder_w4<<<512, 256>>>((const float4*)(w_hh_rest + (size_t)(l - 1) * Gg * Hh),
                                 (float4*)(whhp + (size_t)l * Gg * Hh), Hh / 4);
        reorder_b<<<12, 256>>>(b_rest + (size_t)(l - 1) * Gg, bp + (size_t)l * Gg);
    }

    const float* layin[Ll] = {x, y0, y1, y0};
    float* layout_[Ll]     = {y0, y1, y0, out};
    const bool write_states = (out_size >= RS * Hh + 2 * Ll * Bb * Hh);

    for (int l = 0; l < Ll; l++) {
        int K = (l == 0) ? INP : Hh;
        const float* Wih = (l == 0) ? wih0p : (wihp + (size_t)(l - 1) * Gg * Hh);

        gemm_input<<<dim3(24, 128), 256, SMEMB_G>>>(layin[l], Wih, bp + (size_t)l * Gg, gates, K);

        cudaMemsetAsync(bar, 0, 2 * sizeof(unsigned));
        float* hf = write_states ? (out + (size_t)RS * Hh + (size_t)l * Bb * Hh) : nullptr;
        float* cf = write_states ? (out + (size_t)RS * Hh + (size_t)Ll * Bb * Hh + (size_t)l * Bb * Hh) : nullptr;
        lstm_layer<<<NB, NT, SMEMB_L>>>(gates, whhp + (size_t)l * Gg * Hh, layout_[l], hf, cf);
    }
}